// round 11
// baseline (speedup 1.0000x reference)
#include <cuda_runtime.h>
#include <stdint.h>

typedef unsigned long long ull;

#define OF 28672
#define IF 8192
#define NQ 4
#define GPQ 64
#define CB 448

__device__ float g_part[NQ * OF];
__device__ int   g_cnt[CB];          // zero-init; self-resetting

__device__ const signed char c_xoff[34] = {
    0,1,2,3,4,5,6,7,8,9,10,
    10,11,12,13,14,15,16,17,18,19,20,21,
    21,22,23,24,25,26,27,28,29,30,31};
__device__ const signed char c_e[34] = {
    -10,-13,-16,-19,-12,-15,-18,-10,-13,-16,-19,
    -8,-11,-14,-17,-20,-13,-16,-19,-11,-14,-17,-20,
    -9,-12,-15,-18,-11,-14,-17,-20,-12,-15,-18};

__device__ __forceinline__ float pw2(int e) {
    return __int_as_float((127 + e) << 23);
}

// (v & MASK) | 0x4B000000 in ONE lop3 per 32-bit half, pack, FFMA2.
#define F2(J, M, XP) do { \
    uint32_t mlo_, mhi_; ull mm_; \
    asm("lop3.b32 %0, %1, %2, 0x4B000000, 0xEA;" : "=r"(mlo_) : "r"(vlo), "n"(M)); \
    asm("lop3.b32 %0, %1, %2, 0x4B000000, 0xEA;" : "=r"(mhi_) : "r"(vhi), "n"(M)); \
    asm("mov.b64 %0, {%1, %2};" : "=l"(mm_) : "r"(mlo_), "r"(mhi_)); \
    asm("fma.rn.f32x2 %0, %1, %2, %0;" : "+l"(acc[(J) & 3]) : "l"(mm_), "l"(XP)); \
} while (0)

#define ADD2(ACC, B) asm("add.rn.f32x2 %0, %0, %1;" : "+l"(ACC) : "l"(B))

__global__ void __launch_bounds__(256, 4) fused3_kernel(
    const uint32_t* __restrict__ qw,
    const float* __restrict__ x,
    const float* __restrict__ scales,
    const float* __restrict__ zeros,
    const float* __restrict__ bias,
    float* __restrict__ out)
{
    __shared__ __align__(16) ull smx[GPQ * 40];   // 20.5 KB table
    __shared__ ull part[256];
    __shared__ float s_red[8];
    __shared__ float s_sumxq;
    __shared__ int s_flag;

    const int t = threadIdx.x;
    const int q = blockIdx.y;
    const int xbase = q * 2048;

    // ---- sumx over this quarter ----
    {
        float s = 0.f;
        #pragma unroll
        for (int i = 0; i < 8; i++) s += x[xbase + t + 256 * i];
        #pragma unroll
        for (int o = 16; o; o >>= 1) s += __shfl_xor_sync(~0u, s, o);
        if ((t & 31) == 0) s_red[t >> 5] = s;
    }

    // ---- build 64-group x'' table (duplicated pairs) + Kahan group biases ----
    for (int i = 0; i < 10; i++) {
        int e = t + 256 * i;
        int gl = e / 40, j = e - gl * 40;
        float v = 0.f;
        if (j < 34) {
            v = x[xbase + gl * 32 + c_xoff[j]] * pw2((int)c_e[j]);
        } else if (j < 38) {
            int a = j - 34;
            float ss = 0.f, comp = 0.f;
            for (int j2 = a; j2 < 34; j2 += 4) {
                float vv = x[xbase + gl * 32 + c_xoff[j2]] * pw2((int)c_e[j2]);
                float y = vv - comp;
                float t2 = ss + y;
                comp = (t2 - ss) - y;
                ss = t2;
            }
            v = ss * -8388608.f;   // -2^23 * group-sum
        }
        *(float2*)((char*)smx + (size_t)e * 8) = make_float2(v, v);
    }
    __syncthreads();
    if (t == 0) {
        float a2 = 0.f;
        #pragma unroll
        for (int k = 0; k < 8; k++) a2 += s_red[k];
        s_sumxq = a2;
    }

    // ---- main loop: 2 cols/thread, 8 groups ----
    const int lane = t & 31;
    const int sl = t >> 5;
    const uint2* p = (const uint2*)(qw + (size_t)(3 * (q * GPQ + sl * 8)) * OF
                                       + blockIdx.x * 64) + lane;
    const ulonglong2* xq2 = (const ulonglong2*)(smx + sl * 8 * 40);

    ull acc[4] = {0ull, 0ull, 0ull, 0ull};
    uint2 w0 = p[0], w1 = p[OF / 2], w2 = p[OF];

    #pragma unroll 1
    for (int g = 0; g < 8; g++) {
        p += 3 * (OF / 2);
        uint2 n0 = make_uint2(0u, 0u), n1 = n0, n2 = n0;
        if (g < 7) { n0 = p[0]; n1 = p[OF / 2]; n2 = p[OF]; }

        ulonglong2 xa = xq2[0], xb = xq2[1], xc = xq2[2];
        uint32_t vlo, vhi;

        vlo = w0.x << 10; vhi = w0.y << 10;
        F2(0, 7 << 10, xa.x);  F2(1, 7 << 13, xa.y);  xa = xq2[3];
        F2(2, 7 << 16, xb.x);  F2(3, 7 << 19, xb.y);  xb = xq2[4];
        vlo = w0.x; vhi = w0.y;
        F2(4, 7 << 12, xc.x);  F2(5, 7 << 15, xc.y);  xc = xq2[5];
        F2(6, 7 << 18, xa.x);
        vlo = w0.x >> 11; vhi = w0.y >> 11;
        F2(7, 7 << 10, xa.y);  xa = xq2[6];
        F2(8, 7 << 13, xb.x);  F2(9, 7 << 16, xb.y);  xb = xq2[7];
        F2(10, 3 << 19, xc.x);
        vlo = w1.x << 10; vhi = w1.y << 10;
        F2(11, 1 << 10, xc.y); xc = xq2[8];
        F2(12, 7 << 11, xa.x); F2(13, 7 << 14, xa.y); xa = xq2[9];
        F2(14, 7 << 17, xb.x); F2(15, 7 << 20, xb.y); xb = xq2[10];
        vlo = w1.x; vhi = w1.y;
        F2(16, 7 << 13, xc.x); F2(17, 7 << 16, xc.y); xc = xq2[11];
        F2(18, 7 << 19, xa.x);
        vlo = w1.x >> 11; vhi = w1.y >> 11;
        F2(19, 7 << 11, xa.y); xa = xq2[12];
        F2(20, 7 << 14, xb.x); F2(21, 7 << 17, xb.y); xb = xq2[13];
        F2(22, 1 << 20, xc.x);
        vlo = w2.x << 10; vhi = w2.y << 10;
        F2(23, 3 << 10, xc.y); xc = xq2[14];
        F2(24, 7 << 12, xa.x); F2(25, 7 << 15, xa.y); xa = xq2[15];
        F2(26, 7 << 18, xb.x);
        vlo = w2.x; vhi = w2.y;
        F2(27, 7 << 11, xb.y); xb = xq2[16];
        F2(28, 7 << 14, xc.x); F2(29, 7 << 17, xc.y); xc = xq2[17];
        F2(30, 7 << 20, xa.x);
        vlo = w2.x >> 11; vhi = w2.y >> 11;
        F2(31, 7 << 12, xa.y);
        F2(32, 7 << 15, xb.x); F2(33, 7 << 18, xb.y);

        {   // per-group contamination cancel
            ulonglong2 xd = xq2[18];
            ADD2(acc[0], xc.x); ADD2(acc[1], xc.y);
            ADD2(acc[2], xd.x); ADD2(acc[3], xd.y);
        }

        xq2 += 20;
        w0 = n0; w1 = n1; w2 = n2;
    }

    ADD2(acc[0], acc[1]);
    ADD2(acc[2], acc[3]);
    ADD2(acc[0], acc[2]);
    part[t] = acc[0];
    __syncthreads();

    // ---- per-quarter partial: scale*dot - zeros*sumx_q ----
    if (t < 64) {
        const float* pf = (const float*)part;
        float dot = 0.f;
        #pragma unroll
        for (int s2 = 0; s2 < 8; s2++)
            dot += pf[(s2 * 32 + (t >> 1)) * 2 + (t & 1)];
        const int c = blockIdx.x * 64 + t;
        g_part[q * OF + c] = fmaf(scales[c], dot, -zeros[c] * s_sumxq);
    }
    __threadfence();
    __syncthreads();
    if (t == 0) s_flag = atomicAdd(&g_cnt[blockIdx.x], 1);
    __syncthreads();

    // ---- last arriver of the 4 quarters combines ----
    if (s_flag == 3) {
        if (t == 0) g_cnt[blockIdx.x] = 0;   // reset for next replay
        __threadfence();
        if (t < 64) {
            const int c = blockIdx.x * 64 + t;
            float r = (g_part[c] + g_part[OF + c]) +
                      (g_part[2 * OF + c] + g_part[3 * OF + c]);
            out[c] = bias[c] + r;
        }
    }
}

extern "C" void kernel_launch(void* const* d_in, const int* in_sizes, int n_in,
                              void* d_out, int out_size) {
    const float*    x      = (const float*)d_in[0];
    const uint32_t* qw     = (const uint32_t*)d_in[1];
    const float*    scales = (const float*)d_in[2];
    const float*    zeros  = (const float*)d_in[3];
    const float*    bias   = (const float*)d_in[4];
    float*          out    = (float*)d_out;

    fused3_kernel<<<dim3(CB, NQ), 256>>>(qw, x, scales, zeros, bias, out);
}

// round 12
// speedup vs baseline: 2.0675x; 2.0675x over previous
#include <cuda_runtime.h>
#include <stdint.h>

typedef unsigned long long ull;

#define OF 28672
#define IF 8192

// table: 256 groups x 24 float2 slots (17 x-pairs + 4 neg-bias pairs + 3 pad)
__device__ __align__(16) float g_xs[256 * 48];
__device__ float g_sumred[32];

// pair table: {offA, eA, offB, eB} — field->x mapping per pair
__constant__ int c_pair[17][4] = {
    {0,-10, 1,-13},   // P0  w0<<10
    {2,-16, 3,-19},   // P1  w0<<10
    {4,-12, 5,-15},   // P2  w0
    {7,-10, 8,-13},   // P3  w0>>11
    {9,-16, 10,-19},  // P4  w0>>11
    {6,-18, 14,-20},  // P5  w0 / w1<<10
    {10,-8, 11,-11},  // P6  w1<<10
    {12,-14, 13,-17}, // P7  w1<<10
    {15,-13, 16,-16}, // P8  w1
    {18,-11, 19,-14}, // P9  w1>>11
    {20,-17, 21,-20}, // P10 w1>>11
    {17,-19, 31,-18}, // P11 w1 / w2>>11
    {21,-9, 22,-12},  // P12 w2<<10
    {23,-15, 24,-18}, // P13 w2<<10
    {25,-11, 26,-14}, // P14 w2
    {27,-17, 28,-20}, // P15 w2
    {29,-12, 30,-15}, // P16 w2>>11
};

__device__ __forceinline__ float pw2(int e) {
    return __int_as_float((127 + e) << 23);
}

// prep: blocks 0-23 table, 24-55 sumx partials, 56-167 out=bias
__global__ void prep_kernel(const float* __restrict__ x,
                            const float* __restrict__ bias,
                            float* __restrict__ out) {
    const int b = blockIdx.x, t = threadIdx.x;
    if (b < 24) {
        int s = b * 256 + t;            // 0..6143 = 256 groups x 24 slots
        int g = s / 24, j = s - g * 24;
        float2 v = make_float2(0.f, 0.f);
        if (j < 17) {
            v.x = x[g * 32 + c_pair[j][0]] * pw2(c_pair[j][1]);
            v.y = x[g * 32 + c_pair[j][2]] * pw2(c_pair[j][3]);
        } else if (j < 21) {
            int a = j - 17;
            float sa = 0.f, sb = 0.f;
            for (int k = a; k < 17; k += 4) {
                sa += x[g * 32 + c_pair[k][0]] * pw2(c_pair[k][1]);
                sb += x[g * 32 + c_pair[k][2]] * pw2(c_pair[k][3]);
            }
            v.x = sa * -8388608.f;      // -2^23 * lane sums
            v.y = sb * -8388608.f;
        }
        *(float2*)(g_xs + s * 2) = v;
    } else if (b < 56) {
        __shared__ float red[256];
        int blk = b - 24;
        red[t] = x[blk * 256 + t];
        __syncthreads();
        #pragma unroll
        for (int off = 128; off; off >>= 1) {
            if (t < off) red[t] += red[t + off];
            __syncthreads();
        }
        if (t == 0) g_sumred[blk] = red[0];
    } else {
        int i = (b - 56) * 256 + t;
        if (i < OF) out[i] = bias[i];
    }
}

#define LOP3_OR(D, V, M) asm("lop3.b32 %0, %1, %2, 0x4B000000, 0xEA;" : "=r"(D) : "r"(V), "n"(M))
#define PK(D, LO, HI)    asm("mov.b64 %0, {%1, %2};" : "=l"(D) : "r"(LO), "r"(HI))
#define FMA2(A, B, C)    asm("fma.rn.f32x2 %0, %1, %2, %0;" : "+l"(A) : "l"(B), "l"(C))
#define ADD2(A, B)       asm("add.rn.f32x2 %0, %0, %1;" : "+l"(A) : "l"(B))

// one field-pair, both columns (L=.x col, H=.y col); lanes = two fields, x-pair shared
#define PAIR(K, VAL, VAH, MA, VBL, VBH, MB, XP) do { \
    uint32_t aL_, bL_, aH_, bH_; ull mL_, mH_; \
    LOP3_OR(aL_, VAL, MA); LOP3_OR(bL_, VBL, MB); PK(mL_, aL_, bL_); \
    FMA2(accL[(K) & 3], mL_, XP); \
    LOP3_OR(aH_, VAH, MA); LOP3_OR(bH_, VBH, MB); PK(mH_, aH_, bH_); \
    FMA2(accH[(K) & 3], mH_, XP); \
} while (0)

// GEMV: grid (448, 4), 256 thr. Thread = 2 adjacent columns x 8 K-slices.
__global__ void __launch_bounds__(256, 4) gemv3_kernel(
    const uint32_t* __restrict__ qw,
    const float* __restrict__ scales,
    const float* __restrict__ zeros,
    float* __restrict__ out)
{
    __shared__ __align__(16) ull smx[64 * 24];   // 12 KB quarter table
    __shared__ ull part[512];
    __shared__ float s_sumx;
    const int t = threadIdx.x;
    const int q = blockIdx.y;

    {   // stage quarter table (768 float4)
        const float4* src = (const float4*)g_xs + q * 768;
        float4* dst = (float4*)smx;
        dst[t] = src[t]; dst[t + 256] = src[t + 256]; dst[t + 512] = src[t + 512];
    }
    if (q == 0 && t < 32) {
        float s = g_sumred[t];
        #pragma unroll
        for (int o = 16; o; o >>= 1) s += __shfl_xor_sync(~0u, s, o);
        if (t == 0) s_sumx = s;
    }
    __syncthreads();

    const int lane = t & 31, sl = t >> 5;
    const uint2* p = (const uint2*)(qw + (size_t)(3 * (q * 64 + sl * 8)) * OF
                                       + blockIdx.x * 64) + lane;
    const ulonglong2* xq = (const ulonglong2*)(smx + sl * 8 * 24);

    ull accL[4] = {0,0,0,0}, accH[4] = {0,0,0,0};
    uint2 w0 = p[0], w1 = p[OF / 2], w2 = p[OF];

    #pragma unroll 1
    for (int g = 0; g < 8; g++) {
        p += 3 * (OF / 2);
        uint2 n0 = make_uint2(0u, 0u), n1 = n0, n2 = n0;
        if (g < 7) { n0 = p[0]; n1 = p[OF / 2]; n2 = p[OF]; }

        ulonglong2 c0 = xq[0], c1 = xq[1], c2 = xq[2];
        uint32_t vax = w0.x << 10, vay = w0.y << 10;
        PAIR(0, vax, vay, 7 << 10, vax, vay, 7 << 13, c0.x);
        PAIR(1, vax, vay, 7 << 16, vax, vay, 7 << 19, c0.y);
        ulonglong2 c3 = xq[3];
        PAIR(2, w0.x, w0.y, 7 << 12, w0.x, w0.y, 7 << 15, c1.x);
        uint32_t vcx = w0.x >> 11, vcy = w0.y >> 11;
        PAIR(3, vcx, vcy, 7 << 10, vcx, vcy, 7 << 13, c1.y);
        ulonglong2 c4 = xq[4];
        PAIR(4, vcx, vcy, 7 << 16, vcx, vcy, 3 << 19, c2.x);
        uint32_t uax = w1.x << 10, uay = w1.y << 10;
        PAIR(5, w0.x, w0.y, 7 << 18, uax, uay, 7 << 20, c2.y);
        ulonglong2 c5 = xq[5];
        PAIR(6, uax, uay, 1 << 10, uax, uay, 7 << 11, c3.x);
        PAIR(7, uax, uay, 7 << 14, uax, uay, 7 << 17, c3.y);
        ulonglong2 c6 = xq[6];
        PAIR(8, w1.x, w1.y, 7 << 13, w1.x, w1.y, 7 << 16, c4.x);
        uint32_t ucx = w1.x >> 11, ucy = w1.y >> 11;
        PAIR(9, ucx, ucy, 7 << 11, ucx, ucy, 7 << 14, c4.y);
        ulonglong2 c7 = xq[7];
        PAIR(10, ucx, ucy, 7 << 17, ucx, ucy, 1 << 20, c5.x);
        uint32_t tax = w2.x << 10, tay = w2.y << 10;
        PAIR(12, tax, tay, 3 << 10, tax, tay, 7 << 12, c6.x);
        ulonglong2 c8 = xq[8];
        PAIR(13, tax, tay, 7 << 15, tax, tay, 7 << 18, c6.y);
        PAIR(14, w2.x, w2.y, 7 << 11, w2.x, w2.y, 7 << 14, c7.x);
        ulonglong2 c9 = xq[9];
        PAIR(15, w2.x, w2.y, 7 << 17, w2.x, w2.y, 7 << 20, c7.y);
        uint32_t tcx = w2.x >> 11, tcy = w2.y >> 11;
        PAIR(16, tcx, tcy, 7 << 12, tcx, tcy, 7 << 15, c8.x);
        PAIR(11, w1.x, w1.y, 7 << 19, tcx, tcy, 7 << 18, c5.y);
        ulonglong2 c10 = xq[10];
        ADD2(accL[0], c8.y);  ADD2(accH[0], c8.y);
        ADD2(accL[1], c9.x);  ADD2(accH[1], c9.x);
        ADD2(accL[2], c9.y);  ADD2(accH[2], c9.y);
        ADD2(accL[3], c10.x); ADD2(accH[3], c10.x);

        xq += 12;
        w0 = n0; w1 = n1; w2 = n2;
    }

    ADD2(accL[0], accL[1]); ADD2(accL[2], accL[3]); ADD2(accL[0], accL[2]);
    ADD2(accH[0], accH[1]); ADD2(accH[2], accH[3]); ADD2(accH[0], accH[2]);
    part[t * 2]     = accL[0];
    part[t * 2 + 1] = accH[0];
    __syncthreads();

    if (t < 64) {
        float dot = 0.f;
        #pragma unroll
        for (int s2 = 0; s2 < 8; s2++) {
            ull v = part[(s2 * 32 + (t >> 1)) * 2 + (t & 1)];
            float2 f = *(float2*)&v;
            dot += f.x + f.y;
        }
        const int c = blockIdx.x * 64 + t;
        float val = scales[c] * dot;
        if (q == 0) val = fmaf(-zeros[c], s_sumx, val);
        atomicAdd(out + c, val);
    }
}

extern "C" void kernel_launch(void* const* d_in, const int* in_sizes, int n_in,
                              void* d_out, int out_size) {
    const float*    x      = (const float*)d_in[0];
    const uint32_t* qw     = (const uint32_t*)d_in[1];
    const float*    scales = (const float*)d_in[2];
    const float*    zeros  = (const float*)d_in[3];
    const float*    bias   = (const float*)d_in[4];
    float*          out    = (float*)d_out;

    prep_kernel<<<168, 256>>>(x, bias, out);
    gemv3_kernel<<<dim3(OF / 64, 4), 256>>>(qw, scales, zeros, out);
}

// round 14
// speedup vs baseline: 2.1650x; 1.0471x over previous
#include <cuda_runtime.h>
#include <stdint.h>

typedef unsigned long long ull;

#define OF 28672
#define IF 8192

// table: 256 groups x 20 float2 slots (17 x-pairs + 2 neg-bias pairs + 1 pad)
__device__ __align__(16) float g_xs[256 * 40];
__device__ float g_sumred[32];

// pair table: {offA, eA, offB, eB} — field->x mapping per pair
__constant__ int c_pair[17][4] = {
    {0,-10, 1,-13},   // P0  w0<<10
    {2,-16, 3,-19},   // P1  w0<<10
    {4,-12, 5,-15},   // P2  w0
    {7,-10, 8,-13},   // P3  w0>>11
    {9,-16, 10,-19},  // P4  w0>>11
    {6,-18, 14,-20},  // P5  w0 / w1<<10
    {10,-8, 11,-11},  // P6  w1<<10
    {12,-14, 13,-17}, // P7  w1<<10
    {15,-13, 16,-16}, // P8  w1
    {18,-11, 19,-14}, // P9  w1>>11
    {20,-17, 21,-20}, // P10 w1>>11
    {17,-19, 31,-18}, // P11 w1 / w2>>11
    {21,-9, 22,-12},  // P12 w2<<10
    {23,-15, 24,-18}, // P13 w2<<10
    {25,-11, 26,-14}, // P14 w2
    {27,-17, 28,-20}, // P15 w2
    {29,-12, 30,-15}, // P16 w2>>11
};

__device__ __forceinline__ float pw2(int e) {
    return __int_as_float((127 + e) << 23);
}

// prep: blocks 0-19 table, 20-51 sumx partials, 52-163 out=bias
__global__ void prep_kernel(const float* __restrict__ x,
                            const float* __restrict__ bias,
                            float* __restrict__ out) {
    const int b = blockIdx.x, t = threadIdx.x;
    if (b < 20) {
        int s = b * 256 + t;            // 0..5119 = 256 groups x 20 slots
        int g = s / 20, j = s - g * 20;
        float2 v = make_float2(0.f, 0.f);
        if (j < 17) {
            v.x = x[g * 32 + c_pair[j][0]] * pw2(c_pair[j][1]);
            v.y = x[g * 32 + c_pair[j][2]] * pw2(c_pair[j][3]);
        } else if (j < 19) {
            int a = j - 17;             // 0: even-K pairs, 1: odd-K pairs
            float sa = 0.f, sb = 0.f;
            for (int k = a; k < 17; k += 2) {
                sa += x[g * 32 + c_pair[k][0]] * pw2(c_pair[k][1]);
                sb += x[g * 32 + c_pair[k][2]] * pw2(c_pair[k][3]);
            }
            v.x = sa * -8388608.f;      // -2^23 * lane sums
            v.y = sb * -8388608.f;
        }
        *(float2*)(g_xs + s * 2) = v;
    } else if (b < 52) {
        __shared__ float red[256];
        int blk = b - 20;
        red[t] = x[blk * 256 + t];
        __syncthreads();
        #pragma unroll
        for (int off = 128; off; off >>= 1) {
            if (t < off) red[t] += red[t + off];
            __syncthreads();
        }
        if (t == 0) g_sumred[blk] = red[0];
    } else {
        int i = (b - 52) * 256 + t;
        if (i < OF) out[i] = bias[i];
    }
}

#define LOP3_OR(D, V, M) asm("lop3.b32 %0, %1, %2, 0x4B000000, 0xEA;" : "=r"(D) : "r"(V), "n"(M))
#define PK(D, LO, HI)    asm("mov.b64 %0, {%1, %2};" : "=l"(D) : "r"(LO), "r"(HI))
#define FMA2(A, B, C)    asm("fma.rn.f32x2 %0, %1, %2, %0;" : "+l"(A) : "l"(B), "l"(C))
#define ADD2(A, B)       asm("add.rn.f32x2 %0, %0, %1;" : "+l"(A) : "l"(B))

// one field-pair, both columns; FFMA2 lanes = two fields of one column, shared x-pair
#define PAIR(K, VAL, VAH, MA, VBL, VBH, MB, XP) do { \
    uint32_t aL_, bL_, aH_, bH_; ull mL_, mH_; \
    LOP3_OR(aL_, VAL, MA); LOP3_OR(bL_, VBL, MB); PK(mL_, aL_, bL_); \
    FMA2(accL[(K) & 1], mL_, XP); \
    LOP3_OR(aH_, VAH, MA); LOP3_OR(bH_, VBH, MB); PK(mH_, aH_, bH_); \
    FMA2(accH[(K) & 1], mH_, XP); \
} while (0)

// GEMV: grid (448, 4), 256 thr. Thread = 2 adjacent columns x 8 K-slices.
__global__ void __launch_bounds__(256, 5) gemv3_kernel(
    const uint32_t* __restrict__ qw,
    const float* __restrict__ scales,
    const float* __restrict__ zeros,
    float* __restrict__ out)
{
    __shared__ __align__(16) ull smx[64 * 20];   // 10.2 KB quarter table (20 ull/group)
    __shared__ ull part[512];
    __shared__ float s_sumx;
    const int t = threadIdx.x;
    const int q = blockIdx.y;

    {   // stage quarter table (640 float4 = 10240 B)
        const float4* src = (const float4*)g_xs + q * 640;
        float4* dst = (float4*)smx;
        dst[t] = src[t]; dst[t + 256] = src[t + 256];
        if (t < 128) dst[t + 512] = src[t + 512];
    }
    if (q == 0 && t < 32) {
        float s = g_sumred[t];
        #pragma unroll
        for (int o = 16; o; o >>= 1) s += __shfl_xor_sync(~0u, s, o);
        if (t == 0) s_sumx = s;
    }
    __syncthreads();

    const int lane = t & 31, sl = t >> 5;
    const uint2* p = (const uint2*)(qw + (size_t)(3 * (q * 64 + sl * 8)) * OF
                                       + blockIdx.x * 64) + lane;
    const ulonglong2* xq = (const ulonglong2*)(smx + sl * 8 * 20);

    ull accL[2] = {0, 0}, accH[2] = {0, 0};
    uint2 w0 = p[0], w1 = p[OF / 2], w2 = p[OF];

    #pragma unroll 1
    for (int g = 0; g < 8; g++) {
        p += 3 * (OF / 2);
        uint2 n0 = make_uint2(0u, 0u), n1 = n0, n2 = n0;
        if (g < 7) { n0 = p[0]; n1 = p[OF / 2]; n2 = p[OF]; }

        ulonglong2 c0 = xq[0], c1 = xq[1], c2 = xq[2];
        uint32_t vax = w0.x << 10, vay = w0.y << 10;
        PAIR(0, vax, vay, 7 << 10, vax, vay, 7 << 13, c0.x);
        PAIR(1, vax, vay, 7 << 16, vax, vay, 7 << 19, c0.y);
        ulonglong2 c3 = xq[3];
        PAIR(2, w0.x, w0.y, 7 << 12, w0.x, w0.y, 7 << 15, c1.x);
        uint32_t vcx = w0.x >> 11, vcy = w0.y >> 11;
        PAIR(3, vcx, vcy, 7 << 10, vcx, vcy, 7 << 13, c1.y);
        ulonglong2 c4 = xq[4];
        PAIR(4, vcx, vcy, 7 << 16, vcx, vcy, 3 << 19, c2.x);
        uint32_t uax = w1.x << 10, uay = w1.y << 10;
        PAIR(5, w0.x, w0.y, 7 << 18, uax, uay, 7 << 20, c2.y);
        ulonglong2 c5 = xq[5];
        PAIR(6, uax, uay, 1 << 10, uax, uay, 7 << 11, c3.x);
        PAIR(7, uax, uay, 7 << 14, uax, uay, 7 << 17, c3.y);
        ulonglong2 c6 = xq[6];
        PAIR(8, w1.x, w1.y, 7 << 13, w1.x, w1.y, 7 << 16, c4.x);
        uint32_t ucx = w1.x >> 11, ucy = w1.y >> 11;
        PAIR(9, ucx, ucy, 7 << 11, ucx, ucy, 7 << 14, c4.y);
        ulonglong2 c7 = xq[7];
        PAIR(10, ucx, ucy, 7 << 17, ucx, ucy, 1 << 20, c5.x);
        uint32_t tax = w2.x << 10, tay = w2.y << 10;
        PAIR(12, tax, tay, 3 << 10, tax, tay, 7 << 12, c6.x);
        ulonglong2 c8 = xq[8];
        PAIR(13, tax, tay, 7 << 15, tax, tay, 7 << 18, c6.y);
        PAIR(14, w2.x, w2.y, 7 << 11, w2.x, w2.y, 7 << 14, c7.x);
        ulonglong2 c9 = xq[9];
        PAIR(15, w2.x, w2.y, 7 << 17, w2.x, w2.y, 7 << 20, c7.y);
        uint32_t tcx = w2.x >> 11, tcy = w2.y >> 11;
        PAIR(16, tcx, tcy, 7 << 12, tcx, tcy, 7 << 15, c8.x);
        PAIR(11, w1.x, w1.y, 7 << 19, tcx, tcy, 7 << 18, c5.y);

        // contamination cancel (even-K pairs -> acc[0], odd-K -> acc[1])
        ADD2(accL[0], c8.y); ADD2(accH[0], c8.y);
        ADD2(accL[1], c9.x); ADD2(accH[1], c9.x);

        xq += 10;
        w0 = n0; w1 = n1; w2 = n2;
    }

    ADD2(accL[0], accL[1]);
    ADD2(accH[0], accH[1]);
    part[t * 2]     = accL[0];
    part[t * 2 + 1] = accH[0];
    __syncthreads();

    if (t < 64) {
        float dot = 0.f;
        #pragma unroll
        for (int s2 = 0; s2 < 8; s2++) {
            ull v = part[(s2 * 32 + (t >> 1)) * 2 + (t & 1)];
            float2 f = *(float2*)&v;
            dot += f.x + f.y;
        }
        const int c = blockIdx.x * 64 + t;
        float val = scales[c] * dot;
        if (q == 0) val = fmaf(-zeros[c], s_sumx, val);
        atomicAdd(out + c, val);
    }
}

extern "C" void kernel_launch(void* const* d_in, const int* in_sizes, int n_in,
                              void* d_out, int out_size) {
    const float*    x      = (const float*)d_in[0];
    const uint32_t* qw     = (const uint32_t*)d_in[1];
    const float*    scales = (const float*)d_in[2];
    const float*    zeros  = (const float*)d_in[3];
    const float*    bias   = (const float*)d_in[4];
    float*          out    = (float*)d_out;

    prep_kernel<<<164, 256>>>(x, bias, out);
    gemv3_kernel<<<dim3(OF / 64, 4), 256>>>(qw, scales, zeros, out);
}